// round 11
// baseline (speedup 1.0000x reference)
#include <cuda_runtime.h>
#include <cstdint>
#include <cstddef>

#define BB 4
#define CC 256
#define NN 4096
#define HH 128
#define NSPLIT 8          // column splits of the score GEMM (wave-quantization fix)

typedef unsigned long long ull;

// Scratch: mapped_a / mapped_b row-major [B][N][H]; per-split partial sums; raw diag.
__device__ float g_ma[(size_t)BB * NN * HH];
__device__ float g_mb[(size_t)BB * NN * HH];
__device__ float g_part[NSPLIT][(size_t)BB * NN];
__device__ float g_diagraw[(size_t)BB * NN];

// ---------- packed f32x2 helpers (full-rate FMA on sm_103a) ----------
__device__ __forceinline__ ull pack2(float x) {
    ull r;
    asm("mov.b64 %0, {%1, %1};" : "=l"(r) : "f"(x));
    return r;
}
__device__ __forceinline__ void fma2(ull& d, ull a, ull b) {
    asm("fma.rn.f32x2 %0, %1, %2, %0;" : "+l"(d) : "l"(a), "l"(b));
}
__device__ __forceinline__ ull fma2n(ull a, ull b, ull c) {
    ull d;
    asm("fma.rn.f32x2 %0, %1, %2, %3;" : "=l"(d) : "l"(a), "l"(b), "l"(c));
    return d;
}
__device__ __forceinline__ ull mul2n(ull a, ull b) {
    ull d;
    asm("mul.rn.f32x2 %0, %1, %2;" : "=l"(d) : "l"(a), "l"(b));
    return d;
}
__device__ __forceinline__ ull add2n(ull a, ull b) {
    ull d;
    asm("add.rn.f32x2 %0, %1, %2;" : "=l"(d) : "l"(a), "l"(b));
    return d;
}
__device__ __forceinline__ float2 unpack2(ull v) {
    float2 r;
    asm("mov.b64 {%0, %1}, %2;" : "=f"(r.x), "=f"(r.y) : "l"(v));
    return r;
}

// ---------- FFMA-only exp, scalar (small tails only) ----------
__device__ __forceinline__ float fexp(float s) {
    float t = s * 1.4426950408889634f;
    float z = t + 12582912.0f;                    // 1.5*2^23: round-to-nearest
    int   n = __float_as_int(z) - 0x4B400000;
    float fl = z - 12582912.0f;
    float f = t - fl;                             // frac in [-0.5, 0.5]
    float p = 1.3333558146428443e-3f;
    p = fmaf(p, f, 9.6181291076284771e-3f);
    p = fmaf(p, f, 5.5504108664821580e-2f);
    p = fmaf(p, f, 2.4022650695910072e-1f);
    p = fmaf(p, f, 6.9314718055994531e-1f);
    p = fmaf(p, f, 1.0f);
    return p * __int_as_float((n + 127) << 23);   // * 2^n  (|s| <= ~25 here)
}

// ---------- packed exp: e^{s.x}, e^{s.y} in one f32x2 lane-pair ----------
// Same math as fexp(); 9 fma-pipe issues per PAIR, integer exponent assembly
// rides the ALU pipe and overlaps the FMA-pipe work.
__device__ __forceinline__ ull fexp_pair(ull s2) {
    const ull LOG2E = pack2(1.4426950408889634f);
    const ull MAGIC = pack2(12582912.0f);
    const ull NMAGIC = pack2(-12582912.0f);
    const ull NEG1 = pack2(-1.0f);
    ull t = mul2n(s2, LOG2E);
    ull z = add2n(t, MAGIC);
    ull fl = add2n(z, NMAGIC);
    ull f = fma2n(fl, NEG1, t);                   // frac in [-0.5, 0.5] per lane
    // per-lane scale = 2^n, n = round(t):  bits(z) - 0x4B400000 + 127, << 23
    unsigned lo, hi;
    asm("mov.b64 {%0, %1}, %2;" : "=r"(lo), "=r"(hi) : "l"(z));
    int s0 = ((int)lo - 0x4B3FFF81) << 23;
    int s1 = ((int)hi - 0x4B3FFF81) << 23;
    ull sc;
    asm("mov.b64 %0, {%1, %2};" : "=l"(sc) : "r"(s0), "r"(s1));
    ull p = pack2(1.3333558146428443e-3f);
    p = fma2n(p, f, pack2(9.6181291076284771e-3f));
    p = fma2n(p, f, pack2(5.5504108664821580e-2f));
    p = fma2n(p, f, pack2(2.4022650695910072e-1f));
    p = fma2n(p, f, pack2(6.9314718055994531e-1f));
    p = fma2n(p, f, pack2(1.0f));
    return mul2n(p, sc);
}

// ---------------------------------------------------------------------------
// Phase 1: mapped[b][n][h] = sum_c in[b][c][n] * W[h][c] + bias[h]
// grid (B*N/128, 2): y selects (a) vs (b). 128 n-rows x 128 h-cols per block.
// ---------------------------------------------------------------------------
__global__ __launch_bounds__(256, 1) void map_kernel(const float* __restrict__ ina,
                                                     const float* __restrict__ Wa,
                                                     const float* __restrict__ ba,
                                                     const float* __restrict__ inb,
                                                     const float* __restrict__ Wb,
                                                     const float* __restrict__ bb) {
    __shared__ __align__(16) float Ins[16][128];   // [c-chunk][n]
    __shared__ __align__(16) float Ws[16][132];    // [c-chunk][h], padded
    __shared__ __align__(16) float sbias[128];

    const int which = blockIdx.y;
    const float* in = which ? inb : ina;
    const float* W = which ? Wb : Wa;
    const float* bias = which ? bb : ba;
    float* gout = which ? g_mb : g_ma;

    const int blk = blockIdx.x;
    const int b = blk >> 5;
    const int n0 = (blk & 31) << 7;
    const float* inp = in + (size_t)b * CC * NN;
    const int tid = threadIdx.x;
    const int ty = tid >> 4, tx = tid & 15;

    if (tid < 128) sbias[tid] = bias[tid];

    ull acc2[4][8];
#pragma unroll
    for (int ii = 0; ii < 4; ii++)
#pragma unroll
        for (int j = 0; j < 8; j++) acc2[ii][j] = 0ull;

#pragma unroll 1
    for (int c0 = 0; c0 < CC; c0 += 16) {
        __syncthreads();
#pragma unroll
        for (int s = 0; s < 2; s++) {
            int p = tid + (s << 8);
            int kk = p >> 5;
            int nn = (p & 31) << 2;
            *(float4*)&Ins[kk][nn] =
                *(const float4*)(inp + (size_t)(c0 + kk) * NN + n0 + nn);
        }
#pragma unroll
        for (int u = 0; u < 8; u++) {
            int idx = tid + (u << 8);
            int h = idx >> 4;
            int kk = idx & 15;
            Ws[kk][h] = W[h * CC + c0 + kk];
        }
        __syncthreads();
#pragma unroll
        for (int k = 0; k < 16; k++) {
            const ull* Ap = (const ull*)&Ins[k][ty * 8];
            ull a2[4] = {Ap[0], Ap[1], Ap[2], Ap[3]};
            float4 b0 = *(const float4*)&Ws[k][tx * 8];
            float4 b1 = *(const float4*)&Ws[k][tx * 8 + 4];
            ull bv[8] = {pack2(b0.x), pack2(b0.y), pack2(b0.z), pack2(b0.w),
                         pack2(b1.x), pack2(b1.y), pack2(b1.z), pack2(b1.w)};
#pragma unroll
            for (int ii = 0; ii < 4; ii++)
#pragma unroll
                for (int j = 0; j < 8; j++) fma2(acc2[ii][j], a2[ii], bv[j]);
        }
    }

    float* outp = gout + ((size_t)b * NN + n0) * HH;
#pragma unroll
    for (int ii = 0; ii < 4; ii++) {
        float v0[8], v1[8];
#pragma unroll
        for (int j = 0; j < 8; j++) {
            float2 u = unpack2(acc2[ii][j]);
            float bj = sbias[tx * 8 + j];
            v0[j] = u.x + bj;
            v1[j] = u.y + bj;
        }
        float* o0 = outp + (size_t)(ty * 8 + 2 * ii) * HH + tx * 8;
        *(float4*)o0 = make_float4(v0[0], v0[1], v0[2], v0[3]);
        *(float4*)(o0 + 4) = make_float4(v0[4], v0[5], v0[6], v0[7]);
        float* o1 = o0 + HH;
        *(float4*)o1 = make_float4(v1[0], v1[1], v1[2], v1[3]);
        *(float4*)(o1 + 4) = make_float4(v1[4], v1[5], v1[6], v1[7]);
    }
}

// ---------------------------------------------------------------------------
// Phase 2 (score): grid (B*32 row-tiles, NSPLIT col-splits) = 1024 blocks.
// Block (rt, s) computes rows r0..r0+127 vs cols [s*512, s*512+512):
//   partial S, plus raw diag scores if the diagonal tile lies in this split.
// 8x8 micro-tile on f32x2, double-buffered 16k-deep B chunks, 1 bar/chunk.
// ~135 regs/thread -> 1 block/SM by RF; launch_bounds pinned to avoid spills.
// ---------------------------------------------------------------------------
#define APAD 132
__global__ __launch_bounds__(256, 1) void score_kernel() {
    extern __shared__ float sm[];
    float* Asf = sm;                    // [128 k][APAD] k-major
    float* Bsb0 = Asf + 128 * APAD;     // [16 k][132] chunk buffer 0
    float* Bsb1 = Bsb0 + 16 * 132;      // buffer 1
    float* sred = Bsb1 + 16 * 132;      // [128][17]

    const int rowtile = blockIdx.x;     // [0, B*32)
    const int split = blockIdx.y;       // [0, NSPLIT)
    const int b = rowtile >> 5;
    const int rblk = rowtile & 31;
    const int r0 = rblk << 7;
    const float* Am = g_ma + (size_t)b * NN * HH;
    const float* Bm = g_mb + (size_t)b * NN * HH;
    const int tid = threadIdx.x;
    const int ty = tid >> 4, tx = tid & 15;
    const int G0 = split * 32;          // first chunk index (global g = ct*8+q)
    const int GLAST = G0 + 31;

    // Load A block (128 rows x K=128) transposed into k-major smem.
#pragma unroll
    for (int u = 0; u < 16; u++) {
        int p = tid + (u << 8);
        int row = p >> 5;
        int kq = (p & 31) << 2;
        float4 v = *(const float4*)(Am + (size_t)(r0 + row) * HH + kq);
        Asf[(kq + 0) * APAD + row] = v.x;
        Asf[(kq + 1) * APAD + row] = v.y;
        Asf[(kq + 2) * APAD + row] = v.z;
        Asf[(kq + 3) * APAD + row] = v.w;
    }

    const int c_lo = tid >> 2;                 // col [0,64)
    const int koff = (tid & 3) << 2;           // k offset [0,16)

    ull psum2[4];                               // packed per-row-pair sums
#pragma unroll
    for (int i = 0; i < 4; i++) psum2[i] = 0ull;

    // Chunk g: cols [(g>>3)*128, +128), k [(g&7)*16, +16).
    float4 pf0, pf1;
    {   // prologue: load chunk G0 -> buf0; prefetch chunk G0+1
        int cr0 = (G0 >> 3) << 7;
        pf0 = *(const float4*)(Bm + (size_t)(cr0 + c_lo) * HH + koff);
        pf1 = *(const float4*)(Bm + (size_t)(cr0 + c_lo + 64) * HH + koff);
        Bsb0[(koff + 0) * 132 + c_lo] = pf0.x;
        Bsb0[(koff + 1) * 132 + c_lo] = pf0.y;
        Bsb0[(koff + 2) * 132 + c_lo] = pf0.z;
        Bsb0[(koff + 3) * 132 + c_lo] = pf0.w;
        Bsb0[(koff + 0) * 132 + c_lo + 64] = pf1.x;
        Bsb0[(koff + 1) * 132 + c_lo + 64] = pf1.y;
        Bsb0[(koff + 2) * 132 + c_lo + 64] = pf1.z;
        Bsb0[(koff + 3) * 132 + c_lo + 64] = pf1.w;
        pf0 = *(const float4*)(Bm + (size_t)(cr0 + c_lo) * HH + 16 + koff);
        pf1 = *(const float4*)(Bm + (size_t)(cr0 + c_lo + 64) * HH + 16 + koff);
    }

#pragma unroll 1
    for (int ctl = 0; ctl < 4; ctl++) {
        const int ct = (split << 2) + ctl;      // global col tile [0,32)
        ull acc2[4][8];
#pragma unroll
        for (int ii = 0; ii < 4; ii++)
#pragma unroll
            for (int j = 0; j < 8; j++) acc2[ii][j] = 0ull;

#pragma unroll 1
        for (int q = 0; q < 8; q++) {
            __syncthreads();
            {   // store prefetched chunk g+1 into buf[(q+1)&1]
                float* Bn = ((q + 1) & 1) ? Bsb1 : Bsb0;
                Bn[(koff + 0) * 132 + c_lo] = pf0.x;
                Bn[(koff + 1) * 132 + c_lo] = pf0.y;
                Bn[(koff + 2) * 132 + c_lo] = pf0.z;
                Bn[(koff + 3) * 132 + c_lo] = pf0.w;
                Bn[(koff + 0) * 132 + c_lo + 64] = pf1.x;
                Bn[(koff + 1) * 132 + c_lo + 64] = pf1.y;
                Bn[(koff + 2) * 132 + c_lo + 64] = pf1.z;
                Bn[(koff + 3) * 132 + c_lo + 64] = pf1.w;
            }
            {   // prefetch chunk g+2 (branchless clamp; duplicate never consumed)
                int g2 = G0 + ctl * 8 + q + 2;
                g2 = min(g2, GLAST);
                int cr0 = (g2 >> 3) << 7, k0 = (g2 & 7) << 4;
                pf0 = *(const float4*)(Bm + (size_t)(cr0 + c_lo) * HH + k0 + koff);
                pf1 = *(const float4*)(Bm + (size_t)(cr0 + c_lo + 64) * HH + k0 + koff);
            }
            // compute chunk g from buf[q&1]
            const float* Aq = Asf + (q << 4) * APAD;
            const float* Bc = (q & 1) ? Bsb1 : Bsb0;
#pragma unroll
            for (int k = 0; k < 16; k++) {
                const ull* Ap = (const ull*)(Aq + k * APAD + ty * 8);
                ull a2[4] = {Ap[0], Ap[1], Ap[2], Ap[3]};
                const float* Bk = Bc + k * 132 + tx * 8;
                float4 b0 = *(const float4*)Bk;
                float4 b1 = *(const float4*)(Bk + 4);
                ull bv[8] = {pack2(b0.x), pack2(b0.y), pack2(b0.z), pack2(b0.w),
                             pack2(b1.x), pack2(b1.y), pack2(b1.z), pack2(b1.w)};
#pragma unroll
                for (int ii = 0; ii < 4; ii++)
#pragma unroll
                    for (int j = 0; j < 8; j++) fma2(acc2[ii][j], a2[ii], bv[j]);
            }
        }

        // Tile epilogue: diag capture (tile rblk: in-tile col == in-block row).
        if (ct == rblk && ty == tx) {
            float* dr = g_diagraw + (size_t)b * NN + r0;
#pragma unroll
            for (int ii = 0; ii < 4; ii++) {
                float2 u0 = unpack2(acc2[ii][2 * ii]);
                float2 u1 = unpack2(acc2[ii][2 * ii + 1]);
                dr[ty * 8 + 2 * ii] = u0.x;
                dr[ty * 8 + 2 * ii + 1] = u1.y;
            }
        }
        // Packed exp + packed accumulate (9 fma-pipe issues per score pair).
#pragma unroll
        for (int ii = 0; ii < 4; ii++)
#pragma unroll
            for (int j = 0; j < 8; j++)
                psum2[ii] = add2n(psum2[ii], fexp_pair(acc2[ii][j]));
    }

    // Reduce the 16 column-slice threads per row; write this split's partial.
#pragma unroll
    for (int ii = 0; ii < 4; ii++) {
        float2 u = unpack2(psum2[ii]);
        sred[(ty * 8 + 2 * ii) * 17 + tx] = u.x;
        sred[(ty * 8 + 2 * ii + 1) * 17 + tx] = u.y;
    }
    __syncthreads();
    if (tid < 128) {
        float S = 0.f;
#pragma unroll
        for (int t = 0; t < 16; t++) S += sred[tid * 17 + t];
        g_part[split][(size_t)b * NN + r0 + tid] = S;
    }
}

// ---------------------------------------------------------------------------
// Phase 3 (finish): d[n] = fexp(diagraw[n]) / sum_s part[s][n];
// out_a = d*in_b, out_b = d*in_a. 32 rows/block -> 512 blocks: 3.46 waves of
// fine-grained work for a small wave-quantization tail (memory-bound phase).
// ---------------------------------------------------------------------------
__global__ __launch_bounds__(256) void finish_kernel(const float* __restrict__ ina,
                                                     const float* __restrict__ inb,
                                                     float* __restrict__ outa,
                                                     float* __restrict__ outb) {
    __shared__ __align__(16) float sdiag[32];
    const int blk = blockIdx.x;
    const int b = blk >> 7;                 // 128 blocks per batch
    const int r0 = (blk & 127) << 5;        // 32-row slice
    const int tid = threadIdx.x;

    if (tid < 32) {
        size_t n = (size_t)b * NN + r0 + tid;
        float S = 0.f;
#pragma unroll
        for (int s = 0; s < NSPLIT; s++) S += g_part[s][n];
        sdiag[tid] = fexp(g_diagraw[n]) / S;
    }
    __syncthreads();

    const float* pa = ina + (size_t)b * CC * NN + r0;
    const float* pb = inb + (size_t)b * CC * NN + r0;
    float* oa = outa + (size_t)b * CC * NN + r0;
    float* ob = outb + (size_t)b * CC * NN + r0;
#pragma unroll 2
    for (int p = tid; p < CC * 8; p += 256) {    // 2048 float4s
        int c = p >> 3;
        int nq = (p & 7) << 2;
        size_t off = (size_t)c * NN + nq;
        float4 va = *(const float4*)(pa + off);
        float4 vb = *(const float4*)(pb + off);
        float d0 = sdiag[nq], d1 = sdiag[nq + 1];
        float d2 = sdiag[nq + 2], d3 = sdiag[nq + 3];
        *(float4*)(oa + off) = make_float4(d0 * vb.x, d1 * vb.y, d2 * vb.z, d3 * vb.w);
        *(float4*)(ob + off) = make_float4(d0 * va.x, d1 * va.y, d2 * va.z, d3 * va.w);
    }
}

extern "C" void kernel_launch(void* const* d_in, const int* in_sizes, int n_in,
                              void* d_out, int out_size) {
    (void)in_sizes; (void)n_in; (void)out_size;
    const float* input_a = (const float*)d_in[0];
    const float* input_b = (const float*)d_in[1];
    const float* Wa = (const float*)d_in[2];
    const float* ba = (const float*)d_in[3];
    const float* Wb = (const float*)d_in[4];
    const float* bb = (const float*)d_in[5];
    float* outa = (float*)d_out;
    float* outb = outa + (size_t)BB * CC * NN;

    const int smem_bytes = (128 * APAD + 2 * 16 * 132 + 128 * 17) * 4;  // 92,672 B
    cudaFuncSetAttribute(score_kernel, cudaFuncAttributeMaxDynamicSharedMemorySize,
                         smem_bytes);

    map_kernel<<<dim3(BB * (NN / 128), 2), 256>>>(input_a, Wa, ba, input_b, Wb, bb);
    score_kernel<<<dim3(BB * (NN / 128), NSPLIT), 256, smem_bytes>>>();
    finish_kernel<<<BB * (NN / 32), 256>>>(input_a, input_b, outa, outb);
}